// round 2
// baseline (speedup 1.0000x reference)
#include <cuda_runtime.h>
#include <math.h>

// Problem constants
#define BB 16
#define CC 16
#define HH 256
#define WW 256
#define NGF 16
#define PLANE 65536            // H*W
#define NPIX (BB*PLANE)        // 1,048,576

// Conv tiling
#define TILE_H 16
#define TILE_W 32
#define HALO_H 18
#define HALO_W 34
#define RS 35                  // padded smem row stride
#define CI_CHUNK 24
#define NCO 64
#define WPC 432                // weights per output channel = 48*9
#define CONV_THREADS 512

// Shared memory layout sizes (floats)
#define IN_S_FLOATS (CI_CHUNK*HALO_H*RS)      // 15120
#define W_S_FLOATS  (NCO*WPC)                 // 27648
#define CONV_SMEM_BYTES ((IN_S_FLOATS + W_S_FLOATS)*4)   // 171,072 B

// Device scratch (no allocations allowed)
__device__ double g_stats[5];                 // s0, s1, s00, s01, s11
__device__ float  g_coef[3][NGF];             // a0, a1, d per emb channel
__device__ float  g_off[BB*2*PLANE];          // predicted offsets (B,2,H,W)

// ---------------------------------------------------------------------------
// K0: zero the stats accumulators
// ---------------------------------------------------------------------------
__global__ void zero_stats_kernel() {
    if (threadIdx.x < 5) g_stats[threadIdx.x] = 0.0;
}

// ---------------------------------------------------------------------------
// K1: 5-stat reduction over pre_offset (sum0, sum1, sum00, sum01, sum11)
// ---------------------------------------------------------------------------
__inline__ __device__ double warp_sum(double v) {
    #pragma unroll
    for (int o = 16; o > 0; o >>= 1) v += __shfl_down_sync(0xffffffffu, v, o);
    return v;
}

__global__ void stats_kernel(const float* __restrict__ pre) {
    double s0 = 0, s1 = 0, s00 = 0, s01 = 0, s11 = 0;
    for (int i = blockIdx.x * blockDim.x + threadIdx.x; i < NPIX;
         i += gridDim.x * blockDim.x) {
        int b = i >> 16;
        int p = i & 65535;
        float p0 = pre[(b * 2) * PLANE + p];
        float p1 = pre[(b * 2 + 1) * PLANE + p];
        s0 += p0; s1 += p1;
        s00 += (double)p0 * p0;
        s01 += (double)p0 * p1;
        s11 += (double)p1 * p1;
    }
    s0 = warp_sum(s0); s1 = warp_sum(s1);
    s00 = warp_sum(s00); s01 = warp_sum(s01); s11 = warp_sum(s11);
    if ((threadIdx.x & 31) == 0) {
        atomicAdd(&g_stats[0], s0);
        atomicAdd(&g_stats[1], s1);
        atomicAdd(&g_stats[2], s00);
        atomicAdd(&g_stats[3], s01);
        atomicAdd(&g_stats[4], s11);
    }
}

// ---------------------------------------------------------------------------
// K2: fold 1x1 conv + BatchNorm into per-channel affine coefficients
//     emb_c(p0,p1) = LeakyReLU( a0*p0 + a1*p1 + d )
// ---------------------------------------------------------------------------
__global__ void coef_kernel(const float* __restrict__ embW,
                            const float* __restrict__ embB,
                            const float* __restrict__ gamma,
                            const float* __restrict__ beta) {
    int c = threadIdx.x;
    if (c >= NGF) return;
    const double N = (double)NPIX;
    double m0 = g_stats[0] / N, m1 = g_stats[1] / N;
    double v00 = g_stats[2] / N - m0 * m0;
    double v01 = g_stats[3] / N - m0 * m1;
    double v11 = g_stats[4] / N - m1 * m1;
    double w0 = embW[c * 2 + 0], w1 = embW[c * 2 + 1];
    double var = w0 * w0 * v00 + 2.0 * w0 * w1 * v01 + w1 * w1 * v11;
    double mu = w0 * m0 + w1 * m1 + (double)embB[c];
    double scale = (double)gamma[c] * rsqrt(var + 1e-5);
    g_coef[0][c] = (float)(scale * w0);
    g_coef[1][c] = (float)(scale * w1);
    g_coef[2][c] = (float)((double)beta[c] + scale * ((double)embB[c] - mu));
}

// ---------------------------------------------------------------------------
// K3: fused 3x3 conv (48 -> 64) + LSTM gates + 1x1 offset head.
// One CTA = 32x16 output tile of one batch image. 512 threads.
// ---------------------------------------------------------------------------
extern __shared__ float smem[];

__global__ void __launch_bounds__(CONV_THREADS, 1)
conv_kernel(const float* __restrict__ x, const float* __restrict__ pre,
            const float* __restrict__ h0, const float* __restrict__ c0,
            const float* __restrict__ lstmW, const float* __restrict__ outW,
            const float* __restrict__ outB) {
    float* in_s = smem;
    float* w_s = smem + IN_S_FLOATS;

    const int tid = threadIdx.x;
    const int b = blockIdx.z;
    const int gx0 = blockIdx.x * TILE_W;
    const int gy0 = blockIdx.y * TILE_H;

    // Stage weights (persist across both ci chunks)
    for (int i = tid; i < W_S_FLOATS; i += CONV_THREADS) w_s[i] = lstmW[i];

    const int cg = tid >> 7;            // 0..3 -> output channels cg*16..+15
    const int pb = tid & 127;
    const int trow = pb >> 3;           // 0..15 output row in tile
    const int tx4 = (pb & 7) * 4;       // output col block (4 px)

    float acc[4][16];
    #pragma unroll
    for (int k = 0; k < 4; k++)
        #pragma unroll
        for (int q = 0; q < 16; q++) acc[k][q] = 0.f;

    #pragma unroll 1
    for (int chunk = 0; chunk < 2; chunk++) {
        __syncthreads();
        // Load 24-channel haloed input tile; emb channels computed on the fly
        const int NEL = CI_CHUNK * HALO_H * HALO_W;   // 14688
        for (int i = tid; i < NEL; i += CONV_THREADS) {
            int ci_l = i / (HALO_H * HALO_W);
            int rem = i - ci_l * (HALO_H * HALO_W);
            int r = rem / HALO_W;
            int ccol = rem - r * HALO_W;
            int gy = gy0 + r - 1;
            int gx = gx0 + ccol - 1;
            float v = 0.f;
            if (gy >= 0 && gy < HH && gx >= 0 && gx < WW) {
                int ci = chunk * CI_CHUNK + ci_l;
                int pix = gy * WW + gx;
                if (ci < 16) {
                    v = x[(b * 16 + ci) * PLANE + pix];
                } else if (ci < 32) {
                    int ce = ci - 16;
                    float p0 = pre[(b * 2) * PLANE + pix];
                    float p1 = pre[(b * 2 + 1) * PLANE + pix];
                    float e = g_coef[0][ce] * p0 + g_coef[1][ce] * p1 + g_coef[2][ce];
                    v = e > 0.f ? e : 0.2f * e;
                } else {
                    v = h0[(b * 16 + (ci - 32)) * PLANE + pix];
                }
            }
            in_s[ci_l * (HALO_H * RS) + r * RS + ccol] = v;
        }
        __syncthreads();

        // Main FMA loop: 24 ci x 9 taps x 16 co x 4 px
        const float* wbase = w_s + (cg * 16) * WPC + chunk * CI_CHUNK * 9;
        #pragma unroll 1
        for (int ci = 0; ci < CI_CHUNK; ci++) {
            const float* ip = in_s + ci * (HALO_H * RS) + trow * RS + tx4;
            const float* wp = wbase + ci * 9;
            #pragma unroll
            for (int ty = 0; ty < 3; ty++) {
                float v[6];
                #pragma unroll
                for (int j = 0; j < 6; j++) v[j] = ip[ty * RS + j];
                #pragma unroll
                for (int tx = 0; tx < 3; tx++) {
                    #pragma unroll
                    for (int q = 0; q < 16; q++) {
                        float wv = wp[q * WPC + ty * 3 + tx];
                        #pragma unroll
                        for (int k = 0; k < 4; k++)
                            acc[k][q] = fmaf(v[tx + k], wv, acc[k][q]);
                    }
                }
            }
        }
    }
    __syncthreads();

    // Exchange A through smem so each thread owns all 64 channels of one pixel
    float* A_s = smem;                       // 512*65 floats = 133,120 B (fits)
    const int px_base = trow * TILE_W + tx4;
    #pragma unroll
    for (int k = 0; k < 4; k++)
        #pragma unroll
        for (int q = 0; q < 16; q++)
            A_s[(px_base + k) * 65 + cg * 16 + q] = acc[k][q];
    __syncthreads();

    // Gates + offset head, one pixel per thread
    const int prow = tid >> 5;
    const int pcol = tid & 31;
    const int gy = gy0 + prow;
    const int gx = gx0 + pcol;
    const int pix = gy * WW + gx;
    const float* Ap = A_s + tid * 65;

    float off0 = outB[0];
    float off1 = outB[1];
    #pragma unroll
    for (int ch = 0; ch < 16; ch++) {
        float ai = Ap[ch];
        float af = Ap[16 + ch];
        float ao = Ap[32 + ch];
        float ag = Ap[48 + ch];
        float iv = 1.f / (1.f + __expf(-ai));
        float fv = 1.f / (1.f + __expf(-af));
        float ov = 1.f / (1.f + __expf(-ao));
        float gv = tanhf(ag);
        float c0v = c0[(b * 16 + ch) * PLANE + pix];
        float c1 = fv * c0v + iv * gv;
        float hv = ov * tanhf(c1);
        off0 = fmaf(outW[ch], hv, off0);
        off1 = fmaf(outW[16 + ch], hv, off1);
    }
    g_off[(b * 2) * PLANE + pix] = off0;
    g_off[(b * 2 + 1) * PLANE + pix] = off1;
}

// ---------------------------------------------------------------------------
// K4: bilinear warp of x by predicted offsets.
// NOTE the torch-.view semantics: for pixel p of batch b, the (y,x) offsets
// are the CONTIGUOUS pair at flat indices (2p, 2p+1) of the (2,H*W) offset
// block — NOT (o0[p], o1[p]).
// ---------------------------------------------------------------------------
__global__ void sample_kernel(const float* __restrict__ x,
                              float* __restrict__ out) {
    int n = blockIdx.x * blockDim.x + threadIdx.x;   // B*C*H*W threads
    int pix = n & 65535;
    int bc = n >> 16;              // b*16 + c
    int b = bc >> 4;
    int hh = pix >> 8;
    int ww = pix & 255;

    const float* offb = g_off + b * 2 * PLANE;
    float off0 = offb[2 * pix];        // y-offset (view pair element 0)
    float off1 = offb[2 * pix + 1];    // x-offset (view pair element 1)

    float yc = fminf(fmaxf((float)hh + off0, 0.f), 255.f);
    float xc = fminf(fmaxf((float)ww + off1, 0.f), 255.f);
    float y0f = floorf(yc);
    float x0f = floorf(xc);
    int y0 = (int)y0f;
    int x0 = (int)x0f;
    int y1 = min(y0 + 1, 255);
    int x1 = min(x0 + 1, 255);
    float dy = yc - y0f;
    float dx = xc - x0f;

    const float* img = x + bc * PLANE;
    float v00 = img[y0 * WW + x0];
    float v01 = img[y0 * WW + x1];
    float v10 = img[y1 * WW + x0];
    float v11 = img[y1 * WW + x1];
    float top = v00 + (v01 - v00) * dx;
    float bot = v10 + (v11 - v10) * dx;
    out[n] = top + (bot - top) * dy;
}

// ---------------------------------------------------------------------------
extern "C" void kernel_launch(void* const* d_in, const int* in_sizes, int n_in,
                              void* d_out, int out_size) {
    const float* x     = (const float*)d_in[0];
    const float* pre   = (const float*)d_in[1];
    const float* h0    = (const float*)d_in[2];
    const float* c0    = (const float*)d_in[3];
    const float* embW  = (const float*)d_in[4];
    const float* embB  = (const float*)d_in[5];
    const float* gamma = (const float*)d_in[6];
    const float* beta  = (const float*)d_in[7];
    const float* lstmW = (const float*)d_in[8];
    const float* outW  = (const float*)d_in[9];
    const float* outB  = (const float*)d_in[10];
    float* out = (float*)d_out;

    cudaFuncSetAttribute(conv_kernel,
                         cudaFuncAttributeMaxDynamicSharedMemorySize,
                         CONV_SMEM_BYTES);

    zero_stats_kernel<<<1, 32>>>();
    stats_kernel<<<592, 256>>>(pre);
    coef_kernel<<<1, 16>>>(embW, embB, gamma, beta);
    dim3 cgrid(WW / TILE_W, HH / TILE_H, BB);   // (8, 16, 16)
    conv_kernel<<<cgrid, CONV_THREADS, CONV_SMEM_BYTES>>>(x, pre, h0, c0,
                                                          lstmW, outW, outB);
    sample_kernel<<<(BB * CC * HH * WW) / 256, 256>>>(x, out);
}

// round 4
// speedup vs baseline: 3.0049x; 3.0049x over previous
#include <cuda_runtime.h>
#include <cuda_bf16.h>
#include <math.h>
#include <stdint.h>

// ---------------- problem constants ----------------
#define BB 16
#define CC 16
#define HH 256
#define WW 256
#define NGF 16
#define PLANE 65536
#define NPIX (BB*PLANE)

// ---------------- conv tiling ----------------
#define TW 32                 // tile width (px)
#define TH 16                 // tile height
#define MPX (TW*TH)           // 512 M rows
#define HALO_H 18
#define HALO_W 34
#define CI 48
#define CI_PAD 56             // bf16 elems per pixel (112 B, conflict-free)
#define PIX_STRIDE 112        // bytes
#define CO 64
#define CO_PAD 72             // bf16 elems per weight row (144 B)
#define W_ROW 144             // bytes
#define TAPS 9
#define IN_BYTES (HALO_H*HALO_W*PIX_STRIDE)      // 68,544
#define W_BYTES  (TAPS*CI*W_ROW)                 // 62,208
#define AEX_BYTES (MPX*65*4)                     // 133,120
#define DYN_SMEM 133376
#define CONV_THREADS 512

// ---------------- device scratch ----------------
__device__ double g_stats[5];
__device__ float  g_coef[3][NGF];
__device__ float  g_off[BB*2*PLANE];
__device__ __align__(16) unsigned short g_wb[TAPS*CI*CO_PAD];   // bf16 bits

// ---------------- helpers ----------------
__device__ __forceinline__ uint32_t smem_u32(const void* p) {
    uint32_t a;
    asm("{ .reg .u64 t; cvta.to.shared.u64 t, %1; cvt.u32.u64 %0, t; }"
        : "=r"(a) : "l"(p));
    return a;
}
__device__ __forceinline__ void ldm_x4(uint32_t r[4], uint32_t addr) {
    asm volatile("ldmatrix.sync.aligned.m8n8.x4.shared.b16 {%0,%1,%2,%3}, [%4];"
        : "=r"(r[0]), "=r"(r[1]), "=r"(r[2]), "=r"(r[3]) : "r"(addr));
}
__device__ __forceinline__ void ldm_x2t(uint32_t r[2], uint32_t addr) {
    asm volatile("ldmatrix.sync.aligned.m8n8.x2.trans.shared.b16 {%0,%1}, [%2];"
        : "=r"(r[0]), "=r"(r[1]) : "r"(addr));
}
__device__ __forceinline__ void mma_bf16(float d[4], const uint32_t a[4],
                                         const uint32_t b[2]) {
    asm volatile(
        "mma.sync.aligned.m16n8k16.row.col.f32.bf16.bf16.f32 "
        "{%0,%1,%2,%3}, {%4,%5,%6,%7}, {%8,%9}, {%0,%1,%2,%3};"
        : "+f"(d[0]), "+f"(d[1]), "+f"(d[2]), "+f"(d[3])
        : "r"(a[0]), "r"(a[1]), "r"(a[2]), "r"(a[3]), "r"(b[0]), "r"(b[1]));
}

// ---------------------------------------------------------------------------
// K0-K2: BN-collapse stats + coefficients (proven in passing round)
// ---------------------------------------------------------------------------
__global__ void zero_stats_kernel() {
    if (threadIdx.x < 5) g_stats[threadIdx.x] = 0.0;
}
__inline__ __device__ double warp_sum(double v) {
    #pragma unroll
    for (int o = 16; o > 0; o >>= 1) v += __shfl_down_sync(0xffffffffu, v, o);
    return v;
}
__global__ void stats_kernel(const float* __restrict__ pre) {
    double s0 = 0, s1 = 0, s00 = 0, s01 = 0, s11 = 0;
    for (int i = blockIdx.x * blockDim.x + threadIdx.x; i < NPIX;
         i += gridDim.x * blockDim.x) {
        int b = i >> 16;
        int p = i & 65535;
        float p0 = pre[(b * 2) * PLANE + p];
        float p1 = pre[(b * 2 + 1) * PLANE + p];
        s0 += p0; s1 += p1;
        s00 += (double)p0 * p0;
        s01 += (double)p0 * p1;
        s11 += (double)p1 * p1;
    }
    s0 = warp_sum(s0); s1 = warp_sum(s1);
    s00 = warp_sum(s00); s01 = warp_sum(s01); s11 = warp_sum(s11);
    if ((threadIdx.x & 31) == 0) {
        atomicAdd(&g_stats[0], s0);
        atomicAdd(&g_stats[1], s1);
        atomicAdd(&g_stats[2], s00);
        atomicAdd(&g_stats[3], s01);
        atomicAdd(&g_stats[4], s11);
    }
}
__global__ void coef_kernel(const float* __restrict__ embW,
                            const float* __restrict__ embB,
                            const float* __restrict__ gamma,
                            const float* __restrict__ beta) {
    int c = threadIdx.x;
    if (c >= NGF) return;
    const double N = (double)NPIX;
    double m0 = g_stats[0] / N, m1 = g_stats[1] / N;
    double v00 = g_stats[2] / N - m0 * m0;
    double v01 = g_stats[3] / N - m0 * m1;
    double v11 = g_stats[4] / N - m1 * m1;
    double w0 = embW[c * 2 + 0], w1 = embW[c * 2 + 1];
    double var = w0 * w0 * v00 + 2.0 * w0 * w1 * v01 + w1 * w1 * v11;
    double mu = w0 * m0 + w1 * m1 + (double)embB[c];
    double scale = (double)gamma[c] * rsqrt(var + 1e-5);
    g_coef[0][c] = (float)(scale * w0);
    g_coef[1][c] = (float)(scale * w1);
    g_coef[2][c] = (float)((double)beta[c] + scale * ((double)embB[c] - mu));
}

// ---------------------------------------------------------------------------
// K3a: weight prep — fp32 [64co][48ci][3][3] -> bf16 [tap][ci][co_pad 72]
// ---------------------------------------------------------------------------
__global__ void prep_w_kernel(const float* __restrict__ lstmW) {
    int i = blockIdx.x * blockDim.x + threadIdx.x;
    if (i >= TAPS * CI * CO_PAD) return;
    int tap = i / (CI * CO_PAD);
    int r = i - tap * (CI * CO_PAD);
    int ci = r / CO_PAD;
    int co = r - ci * CO_PAD;
    float v = (co < CO) ? lstmW[co * (CI * 9) + ci * 9 + tap] : 0.f;
    g_wb[i] = __bfloat16_as_ushort(__float2bfloat16(v));
}

// ---------------------------------------------------------------------------
// K3b: HMMA fused conv + gates + offset head.
// CTA = 512 threads, 32x16 px tile, GEMM M=512 N=64 K=432. Grid = 2048.
// ---------------------------------------------------------------------------
extern __shared__ uint8_t cv_smem[];

__global__ void __launch_bounds__(CONV_THREADS, 1)
tconv_kernel(const float* __restrict__ x, const float* __restrict__ pre,
             const float* __restrict__ h0, const float* __restrict__ c0,
             const float* __restrict__ outW, const float* __restrict__ outB) {
    const int tid = threadIdx.x;
    const int b = blockIdx.z;
    const int x0 = blockIdx.x * TW;
    const int y0 = blockIdx.y * TH;

    __nv_bfloat16* in_s16 = (__nv_bfloat16*)cv_smem;
    uint8_t* w_s = cv_smem + IN_BYTES;

    // ---- stage weights (L2-resident source) ----
    {
        const uint4* src = (const uint4*)g_wb;
        uint4* dst = (uint4*)w_s;
        #pragma unroll
        for (int i = tid; i < W_BYTES / 16; i += CONV_THREADS) dst[i] = src[i];
    }

    // ---- stage input tile, channel-last [y][x][ci], emb on the fly ----
    for (int t = tid; t < HALO_H * CI; t += CONV_THREADS) {
        int y = t / CI, ci = t - y * CI;
        int gy = y0 + y - 1;
        bool yok = (gy >= 0 && gy < HH);
        const float* srcp;
        float ca = 0.f, cb2 = 0.f, cd = 0.f;
        int mode;
        if (ci < 16) { mode = 0; srcp = x + (b * 16 + ci) * PLANE; }
        else if (ci < 32) {
            mode = 1;
            int ce = ci - 16;
            ca = g_coef[0][ce]; cb2 = g_coef[1][ce]; cd = g_coef[2][ce];
            srcp = pre + (b * 2) * PLANE;
        } else { mode = 2; srcp = h0 + (b * 16 + (ci - 32)) * PLANE; }

        #pragma unroll 2
        for (int xi = 0; xi < HALO_W; xi++) {
            int gx = x0 + xi - 1;
            float v = 0.f;
            if (yok && gx >= 0 && gx < WW) {
                int pix = gy * WW + gx;
                if (mode == 1) {
                    float p0 = srcp[pix];
                    float p1 = srcp[PLANE + pix];
                    float e = fmaf(ca, p0, fmaf(cb2, p1, cd));
                    v = e > 0.f ? e : 0.2f * e;
                } else {
                    v = srcp[pix];
                }
            }
            in_s16[(y * HALO_W + xi) * CI_PAD + ci] = __float2bfloat16(v);
        }
    }
    __syncthreads();

    // ---- main HMMA loop ----
    const int lane = tid & 31;
    const int wid = tid >> 5;
    const int wm = wid >> 2;          // 0..3 : M quarter (128 px)
    const int wn = wid & 3;           // 0..3 : co group (16 co)

    float d[8][2][4];
    #pragma unroll
    for (int mt = 0; mt < 8; mt++)
        #pragma unroll
        for (int nt = 0; nt < 2; nt++)
            #pragma unroll
            for (int q = 0; q < 4; q++) d[mt][nt][q] = 0.f;

    const uint32_t in_base = smem_u32(cv_smem);
    const uint32_t w_base = in_base + IN_BYTES + (uint32_t)(wn * 16) * 2;
    const int ar = lane & 15;         // A matrix row within tile
    const int kh = lane >> 4;         // A k-half

    #pragma unroll 1
    for (int tap = 0; tap < TAPS; tap++) {
        const int dy = tap / 3 - 1, dx = tap % 3 - 1;
        #pragma unroll
        for (int cig = 0; cig < 3; cig++) {
            uint32_t baddr = w_base +
                (uint32_t)(tap * (CI * W_ROW) + (cig * 16 + (lane & 15)) * W_ROW);
            uint32_t bf0[2], bf1[2];
            ldm_x2t(bf0, baddr);
            ldm_x2t(bf1, baddr + 16);
            #pragma unroll
            for (int mt = 0; mt < 8; mt++) {
                const int gmt = wm * 8 + mt;
                const int y_in = (gmt >> 1) + dy + 1;
                const int x_in = (gmt & 1) * 16 + ar + dx + 1;
                uint32_t aaddr = in_base +
                    (uint32_t)((y_in * HALO_W + x_in) * PIX_STRIDE
                               + cig * 32 + kh * 16);
                uint32_t a[4];
                ldm_x4(a, aaddr);
                mma_bf16(d[mt][0], a, bf0);
                mma_bf16(d[mt][1], a, bf1);
            }
        }
    }
    __syncthreads();

    // ---- exchange D through smem: A_ex[px][co], stride 65 ----
    float* A_ex = (float*)cv_smem;
    {
        const int row0 = lane >> 2;
        const int colb = (lane & 3) * 2;
        #pragma unroll
        for (int mt = 0; mt < 8; mt++) {
            const int gmt = wm * 8 + mt;
            #pragma unroll
            for (int nt = 0; nt < 2; nt++) {
                const int co = wn * 16 + nt * 8 + colb;
                const int p0 = gmt * 16 + row0;
                A_ex[p0 * 65 + co]       = d[mt][nt][0];
                A_ex[p0 * 65 + co + 1]   = d[mt][nt][1];
                A_ex[(p0 + 8) * 65 + co]     = d[mt][nt][2];
                A_ex[(p0 + 8) * 65 + co + 1] = d[mt][nt][3];
            }
        }
    }
    __syncthreads();

    // ---- gates + offset head, one pixel per thread ----
    {
        const int p = tid;
        const int py = y0 + (p >> 5);
        const int pxx = x0 + (p & 31);
        const int pix = py * WW + pxx;
        const float* Ap = A_ex + p * 65;
        float off0 = outB[0], off1 = outB[1];
        #pragma unroll
        for (int ch = 0; ch < 16; ch++) {
            float ai = Ap[ch];
            float af = Ap[16 + ch];
            float ao = Ap[32 + ch];
            float ag = Ap[48 + ch];
            float iv = 1.f / (1.f + __expf(-ai));
            float fv = 1.f / (1.f + __expf(-af));
            float ov = 1.f / (1.f + __expf(-ao));
            float gv = tanhf(ag);
            float c0v = c0[(b * 16 + ch) * PLANE + pix];
            float c1 = fv * c0v + iv * gv;
            float hv = ov * tanhf(c1);
            off0 = fmaf(outW[ch], hv, off0);
            off1 = fmaf(outW[16 + ch], hv, off1);
        }
        g_off[(b * 2) * PLANE + pix] = off0;
        g_off[(b * 2 + 1) * PLANE + pix] = off1;
    }
}

// ---------------------------------------------------------------------------
// K4: bilinear warp (torch-.view pair semantics: flat indices 2p, 2p+1)
// ---------------------------------------------------------------------------
__global__ void sample_kernel(const float* __restrict__ x,
                              float* __restrict__ out) {
    int n = blockIdx.x * blockDim.x + threadIdx.x;
    int pix = n & 65535;
    int bc = n >> 16;
    int b = bc >> 4;
    int hh = pix >> 8;
    int ww = pix & 255;

    const float* offb = g_off + b * 2 * PLANE;
    float off0 = offb[2 * pix];
    float off1 = offb[2 * pix + 1];

    float yc = fminf(fmaxf((float)hh + off0, 0.f), 255.f);
    float xc = fminf(fmaxf((float)ww + off1, 0.f), 255.f);
    float y0f = floorf(yc);
    float x0f = floorf(xc);
    int y0 = (int)y0f;
    int x0 = (int)x0f;
    int y1 = min(y0 + 1, 255);
    int x1 = min(x0 + 1, 255);
    float dy = yc - y0f;
    float dx = xc - x0f;

    const float* img = x + bc * PLANE;
    float v00 = img[y0 * WW + x0];
    float v01 = img[y0 * WW + x1];
    float v10 = img[y1 * WW + x0];
    float v11 = img[y1 * WW + x1];
    float top = v00 + (v01 - v00) * dx;
    float bot = v10 + (v11 - v10) * dx;
    out[n] = top + (bot - top) * dy;
}

// ---------------------------------------------------------------------------
extern "C" void kernel_launch(void* const* d_in, const int* in_sizes, int n_in,
                              void* d_out, int out_size) {
    const float* x     = (const float*)d_in[0];
    const float* pre   = (const float*)d_in[1];
    const float* h0    = (const float*)d_in[2];
    const float* c0    = (const float*)d_in[3];
    const float* embW  = (const float*)d_in[4];
    const float* embB  = (const float*)d_in[5];
    const float* gamma = (const float*)d_in[6];
    const float* beta  = (const float*)d_in[7];
    const float* lstmW = (const float*)d_in[8];
    const float* outW  = (const float*)d_in[9];
    const float* outB  = (const float*)d_in[10];
    float* out = (float*)d_out;

    cudaFuncSetAttribute(tconv_kernel,
                         cudaFuncAttributeMaxDynamicSharedMemorySize, DYN_SMEM);

    zero_stats_kernel<<<1, 32>>>();
    stats_kernel<<<592, 256>>>(pre);
    coef_kernel<<<1, 16>>>(embW, embB, gamma, beta);
    prep_w_kernel<<<(TAPS * CI * CO_PAD + 255) / 256, 256>>>(lstmW);
    dim3 cgrid(WW / TW, HH / TH, BB);   // (8, 16, 16) = 2048
    tconv_kernel<<<cgrid, CONV_THREADS, DYN_SMEM>>>(x, pre, h0, c0, outW, outB);
    sample_kernel<<<(BB * CC * HH * WW) / 256, 256>>>(x, out);
}